// round 1
// baseline (speedup 1.0000x reference)
#include <cuda_runtime.h>
#include <cuda_bf16.h>

// HarmonicMixing: out[b,t,c] = x[c]
//   + sum_o [c % s_o == 0] * sig(uw[o]) * x[c / s_o]          (s_o = 2,4,8)
//   + sum_o [1 <= c < D/s_o] * sig(dw[o]) * sum_{i=c*s_o}^{c*s_o+s_o-1} x[i]
// One CTA per row of D_MODEL=1024 floats; row staged in smem.

#define D_MODEL 1024
#define THREADS 256   // each thread owns one float4 (4 elements)

__global__ void __launch_bounds__(THREADS)
harmonic_mixing_kernel(const float* __restrict__ x,
                       const float* __restrict__ up_w,
                       const float* __restrict__ down_w,
                       float* __restrict__ out)
{
    __shared__ float s[D_MODEL];
    __shared__ float wgt[6];   // wgt[0..2]=sigmoid(up), wgt[3..5]=sigmoid(down)

    const int t = threadIdx.x;
    const long long row = blockIdx.x;

    // Stage the row: 256 x LDG.128 -> STS.128
    const float4* xr = reinterpret_cast<const float4*>(x + row * (long long)D_MODEL);
    float4 v = xr[t];
    reinterpret_cast<float4*>(s)[t] = v;

    // 6 threads compute the 6 sigmoids (once per block; avoids per-thread MUFU storm)
    if (t < 6) {
        float w = (t < 3) ? up_w[t] : down_w[t - 3];
        wgt[t] = 1.0f / (1.0f + expf(-w));
    }
    __syncthreads();

    const float u0 = wgt[0], u1 = wgt[1], u2 = wgt[2];
    const float d0 = wgt[3], d1 = wgt[4], d2 = wgt[5];

    const float2* s2 = reinterpret_cast<const float2*>(s);
    const float4* s4 = reinterpret_cast<const float4*>(s);

    const int c0 = t * 4;
    float4 o;
    float* op = reinterpret_cast<float*>(&o);

    #pragma unroll
    for (int k = 0; k < 4; k++) {
        const int c = c0 + k;
        float r = s[c];

        // up contributions: c must be a multiple of the stride
        if ((c & 1) == 0) r += u0 * s[c >> 1];
        if ((c & 3) == 0) r += u1 * s[c >> 2];
        if ((c & 7) == 0) r += u2 * s[c >> 3];

        // down contributions: target c in [1, D/stride), window sum of stride sources
        if (c >= 1 && c < (D_MODEL / 2)) {
            float2 a = s2[c];
            r += d0 * (a.x + a.y);
        }
        if (c >= 1 && c < (D_MODEL / 4)) {
            float4 a = s4[c];
            r += d1 * ((a.x + a.y) + (a.z + a.w));
        }
        if (c >= 1 && c < (D_MODEL / 8)) {
            float4 a = s4[2 * c];
            float4 b = s4[2 * c + 1];
            r += d2 * (((a.x + a.y) + (a.z + a.w)) + ((b.x + b.y) + (b.z + b.w)));
        }
        op[k] = r;
    }

    reinterpret_cast<float4*>(out + row * (long long)D_MODEL)[t] = o;
}

extern "C" void kernel_launch(void* const* d_in, const int* in_sizes, int n_in,
                              void* d_out, int out_size)
{
    const float* x  = (const float*)d_in[0];
    const float* uw = (const float*)d_in[1];
    const float* dw = (const float*)d_in[2];
    float* out = (float*)d_out;

    const int rows = in_sizes[0] / D_MODEL;   // 8 * 4096 = 32768
    harmonic_mixing_kernel<<<rows, THREADS>>>(x, uw, dw, out);
}

// round 2
// speedup vs baseline: 1.7076x; 1.7076x over previous
#include <cuda_runtime.h>
#include <cuda_bf16.h>

// HarmonicMixing, D=1024, strides 2/4/8.
// out[c] = x[c]
//        + sum_o [c % s == 0] * sig(uw[o]) * x[c/s]
//        + sum_o [1 <= c < D/s] * sig(dw[o]) * (sum of x[c*s .. c*s+s-1])
//
// Strategy: each thread owns 4 contiguous elements (one float4).
// Hierarchical pair sums S1/S2/S3 computed in registers (+1 shfl for S3),
// staged in smem so the down pass is a single conflict-free float4 read per level.
// Only x[0:512] is staged for the up gathers. No element of x is LDS'd twice.

#define D 1024
#define TPR 256          // threads per row
#define ROWS_PER_CTA 2
#define THREADS (TPR * ROWS_PER_CTA)

// per-row smem floats: x[0:512] | S1[512] | S2[256] | S3[128]
#define ROW_SMEM (512 + 512 + 256 + 128)

__global__ void __launch_bounds__(THREADS)
harmonic_mixing_kernel(const float* __restrict__ x,
                       const float* __restrict__ up_w,
                       const float* __restrict__ down_w,
                       float* __restrict__ out)
{
    __shared__ __align__(16) float smem[ROWS_PER_CTA][ROW_SMEM];
    __shared__ float wgt[6];

    const int tid = threadIdx.x;
    const int t   = tid & (TPR - 1);   // element-group id within row
    const int r   = tid >> 8;          // which row of this CTA
    const long long row = (long long)blockIdx.x * ROWS_PER_CTA + r;

    float* sx  = smem[r];
    float* sS1 = sx  + 512;
    float* sS2 = sS1 + 512;
    float* sS3 = sS2 + 256;

    // Load: thread t owns x[4t .. 4t+3]
    const float4 v = reinterpret_cast<const float4*>(x + row * (long long)D)[t];

    // 6 threads compute the 6 sigmoids once per CTA
    if (tid < 6) {
        float w = (tid < 3) ? up_w[tid] : down_w[tid - 3];
        wgt[tid] = 1.0f / (1.0f + expf(-w));
    }

    // Hierarchical window sums (registers; S3 via one shuffle)
    const float S1a = v.x + v.y;          // S1[2t]
    const float S1b = v.z + v.w;          // S1[2t+1]
    const float S2v = S1a + S1b;          // S2[t]
    const float S2n = __shfl_xor_sync(0xffffffffu, S2v, 1);
    const float S3v = S2v + S2n;          // for even t: S3[t>>1]

    if (t < 128) reinterpret_cast<float4*>(sx)[t] = v;        // x[0:512]
    reinterpret_cast<float2*>(sS1)[t] = make_float2(S1a, S1b);
    sS2[t] = S2v;
    if ((t & 1) == 0) sS3[t >> 1] = S3v;

    __syncthreads();

    const float u0 = wgt[0], u1 = wgt[1], u2 = wgt[2];
    const float d0 = wgt[3], d1 = wgt[4], d2 = wgt[5];

    float r0 = v.x, r1 = v.y, r2 = v.z, r3 = v.w;

    // ---- up contributions (c = 4t+k) ----
    // stride 2: c=4t -> x[2t], c=4t+2 -> x[2t+1]  (one float2, conflict-free)
    {
        float2 xu = reinterpret_cast<const float2*>(sx)[t];
        r0 += u0 * xu.x;
        r2 += u0 * xu.y;
    }
    // stride 4: c=4t -> x[t]  (conflict-free scalar)
    r0 += u1 * sx[t];
    // stride 8: c=4t, 8 | c  iff t even -> x[t/2]  (pair-broadcast, conflict-free)
    if ((t & 1) == 0) r0 += u2 * sx[t >> 1];

    // ---- down contributions: out[c] += d_o * S_o[c], 1 <= c < D/s ----
    if (t < 128) {                         // c in [0,512): S1[4t..4t+3]
        float4 a = reinterpret_cast<const float4*>(sS1)[t];
        r0 += d0 * a.x; r1 += d0 * a.y; r2 += d0 * a.z; r3 += d0 * a.w;
    }
    if (t < 64) {                          // c in [0,256): S2
        float4 a = reinterpret_cast<const float4*>(sS2)[t];
        r0 += d1 * a.x; r1 += d1 * a.y; r2 += d1 * a.z; r3 += d1 * a.w;
    }
    if (t < 32) {                          // c in [0,128): S3
        float4 a = reinterpret_cast<const float4*>(sS3)[t];
        r0 += d2 * a.x; r1 += d2 * a.y; r2 += d2 * a.z; r3 += d2 * a.w;
    }
    if (t == 0) {
        // c = 0 is excluded from down targets; undo the three adds
        r0 -= d0 * S1a + d1 * S2v + d2 * S3v;
    }

    reinterpret_cast<float4*>(out + row * (long long)D)[t] =
        make_float4(r0, r1, r2, r3);
}

extern "C" void kernel_launch(void* const* d_in, const int* in_sizes, int n_in,
                              void* d_out, int out_size)
{
    const float* x  = (const float*)d_in[0];
    const float* uw = (const float*)d_in[1];
    const float* dw = (const float*)d_in[2];
    float* out = (float*)d_out;

    const int rows = in_sizes[0] / D;             // 8 * 4096 = 32768
    const int grid = rows / ROWS_PER_CTA;         // 16384
    harmonic_mixing_kernel<<<grid, THREADS>>>(x, uw, dw, out);
}

// round 3
// speedup vs baseline: 1.8534x; 1.0854x over previous
#include <cuda_runtime.h>
#include <cuda_bf16.h>

// HarmonicMixing, D=1024, strides 2/4/8.
// out[c] = x[c]
//        + sum_o [c % s == 0] * sig(uw[o]) * x[c/s]
//        + sum_o [1 <= c < D/s] * sig(dw[o]) * (sum of x[c*s .. c*s+s-1])
//
// R3: 2 rows per thread (ILP=2) to double outstanding LDG bytes per warp and
// amortize the barrier. 512 threads handle 4 rows per CTA.
// Per-row scheme unchanged from R2: hierarchical pair sums S1/S2/S3 in regs
// (+1 shfl for S3), staged in smem, conflict-free float4 consumption.

#define D 1024
#define TPR 256                 // threads per row
#define THREADS 512
#define RPC 4                   // rows per CTA
#define ROW_SMEM (512 + 512 + 256 + 128)   // x[0:512] | S1[512] | S2[256] | S3[128]

struct RowSums { float S1a, S2v, S3v; };

// Produce phase: register sums + smem staging for one row.
static __device__ __forceinline__
RowSums produce_row(const float4 v, float* __restrict__ srow, int t)
{
    float* sx  = srow;
    float* sS1 = sx  + 512;
    float* sS2 = sS1 + 512;
    float* sS3 = sS2 + 256;

    const float S1a = v.x + v.y;            // S1[2t]
    const float S1b = v.z + v.w;            // S1[2t+1]
    const float S2v = S1a + S1b;            // S2[t]
    const float S2n = __shfl_xor_sync(0xffffffffu, S2v, 1);
    const float S3v = S2v + S2n;            // for even t: S3[t>>1]

    if (t < 128) reinterpret_cast<float4*>(sx)[t] = v;   // x[0:512]
    reinterpret_cast<float2*>(sS1)[t] = make_float2(S1a, S1b);
    sS2[t] = S2v;
    if ((t & 1) == 0) sS3[t >> 1] = S3v;

    return RowSums{S1a, S2v, S3v};
}

// Consume phase: compute the 4 outputs for thread t of one row.
static __device__ __forceinline__
float4 consume_row(const float4 v, const float* __restrict__ srow, int t,
                   float u0, float u1, float u2,
                   float d0, float d1, float d2, RowSums rs)
{
    const float* sx  = srow;
    const float* sS1 = sx  + 512;
    const float* sS2 = sS1 + 512;
    const float* sS3 = sS2 + 256;

    float r0 = v.x, r1 = v.y, r2 = v.z, r3 = v.w;

    // up: c = 4t (+2)
    {
        float2 xu = reinterpret_cast<const float2*>(sx)[t];
        r0 += u0 * xu.x;                    // stride 2 at c=4t
        r2 += u0 * xu.y;                    // stride 2 at c=4t+2
    }
    r0 += u1 * sx[t];                       // stride 4 at c=4t
    if ((t & 1) == 0) r0 += u2 * sx[t >> 1];  // stride 8 (only 8|c)

    // down: out[c] += d_o * S_o[c] for 1 <= c < D/s
    if (t < 128) {
        float4 a = reinterpret_cast<const float4*>(sS1)[t];
        r0 += d0 * a.x; r1 += d0 * a.y; r2 += d0 * a.z; r3 += d0 * a.w;
    }
    if (t < 64) {
        float4 a = reinterpret_cast<const float4*>(sS2)[t];
        r0 += d1 * a.x; r1 += d1 * a.y; r2 += d1 * a.z; r3 += d1 * a.w;
    }
    if (t < 32) {
        float4 a = reinterpret_cast<const float4*>(sS3)[t];
        r0 += d2 * a.x; r1 += d2 * a.y; r2 += d2 * a.z; r3 += d2 * a.w;
    }
    if (t == 0) {
        // c = 0 is not a down target; undo the three adds
        r0 -= d0 * rs.S1a + d1 * rs.S2v + d2 * rs.S3v;
    }
    return make_float4(r0, r1, r2, r3);
}

__global__ void __launch_bounds__(THREADS)
harmonic_mixing_kernel(const float* __restrict__ x,
                       const float* __restrict__ up_w,
                       const float* __restrict__ down_w,
                       float* __restrict__ out)
{
    __shared__ __align__(16) float smem[RPC][ROW_SMEM];
    __shared__ float wgt[6];

    const int tid  = threadIdx.x;
    const int t    = tid & (TPR - 1);
    const int half = tid >> 8;                          // 0 or 1

    const long long rowA = (long long)blockIdx.x * RPC + half;
    const long long rowB = rowA + 2;

    // Front-batched independent loads (MLP = 2)
    const float4 vA = reinterpret_cast<const float4*>(x + rowA * (long long)D)[t];
    const float4 vB = reinterpret_cast<const float4*>(x + rowB * (long long)D)[t];

    if (tid < 6) {
        float w = (tid < 3) ? up_w[tid] : down_w[tid - 3];
        wgt[tid] = 1.0f / (1.0f + expf(-w));
    }

    RowSums rsA = produce_row(vA, smem[half],     t);
    RowSums rsB = produce_row(vB, smem[half + 2], t);

    __syncthreads();

    const float u0 = wgt[0], u1 = wgt[1], u2 = wgt[2];
    const float d0 = wgt[3], d1 = wgt[4], d2 = wgt[5];

    float4 oA = consume_row(vA, smem[half],     t, u0, u1, u2, d0, d1, d2, rsA);
    reinterpret_cast<float4*>(out + rowA * (long long)D)[t] = oA;

    float4 oB = consume_row(vB, smem[half + 2], t, u0, u1, u2, d0, d1, d2, rsB);
    reinterpret_cast<float4*>(out + rowB * (long long)D)[t] = oB;
}

extern "C" void kernel_launch(void* const* d_in, const int* in_sizes, int n_in,
                              void* d_out, int out_size)
{
    const float* x  = (const float*)d_in[0];
    const float* uw = (const float*)d_in[1];
    const float* dw = (const float*)d_in[2];
    float* out = (float*)d_out;

    const int rows = in_sizes[0] / D;       // 32768
    const int grid = rows / RPC;            // 8192
    harmonic_mixing_kernel<<<grid, THREADS>>>(x, uw, dw, out);
}

// round 5
// speedup vs baseline: 2.0250x; 1.0926x over previous
#include <cuda_runtime.h>
#include <cuda_bf16.h>

// HarmonicMixing, D=1024, strides 2/4/8.
// out[c] = x[c]
//        + sum_o [c % s == 0] * sig(uw[o]) * x[c/s]
//        + sum_o [1 <= c < D/s] * sig(dw[o]) * (sum of x[c*s .. c*s+s-1])
//
// R5: warp-per-row (MLP=8, no CTA barrier), with the R4 bug fixed:
// S1/S2/S3 are produced from the FULL row (all 8 iterations), while only
// x[0:512] is staged (that's all the up gathers ever read).

#define D 1024
#define WARPS_PER_CTA 8
#define THREADS 256
// slab floats: x[512] | S1[512] | S2[256] | S3[128] | wgt[8]  = 1416
#define SLAB 1416

__global__ void __launch_bounds__(THREADS, 4)
harmonic_mixing_kernel(const float* __restrict__ x,
                       const float* __restrict__ up_w,
                       const float* __restrict__ down_w,
                       float* __restrict__ out)
{
    __shared__ __align__(16) float smem[WARPS_PER_CTA][SLAB];

    const int w = threadIdx.x >> 5;
    const int l = threadIdx.x & 31;
    const long long row = (long long)blockIdx.x * WARPS_PER_CTA + w;

    float* sx   = smem[w];
    float* sS1  = sx   + 512;
    float* sS2  = sS1  + 512;
    float* sS3  = sS2  + 256;
    float* swgt = sS3  + 128;

    // Front-batched loads: iter i covers elements [128i, 128i+128),
    // thread l owns elements 128i + 4l .. 4l+3  (global group t = 32i + l).
    const float4* xr = reinterpret_cast<const float4*>(x + row * (long long)D);
    float4 v0 = xr[l];
    float4 v1 = xr[l + 32];
    float4 v2 = xr[l + 64];
    float4 v3 = xr[l + 96];
    float4 v4 = xr[l + 128];
    float4 v5 = xr[l + 160];
    float4 v6 = xr[l + 192];
    float4 v7 = xr[l + 224];

    // 6 sigmoids per warp (lanes 0..5), broadcast through the slab.
    if (l < 6) {
        float wv = (l < 3) ? up_w[l] : down_w[l - 3];
        swgt[l] = 1.0f / (1.0f + expf(-wv));
    }

    // Produce phase — sums over the FULL row; x staged only for i<4
    // (up gathers read at most x[511]).
#define PRODUCE(i, v)                                                      \
    {                                                                      \
        if ((i) < 4) reinterpret_cast<float4*>(sx)[32 * (i) + l] = (v);    \
        float _a = (v).x + (v).y, _b = (v).z + (v).w;  /* S1[2t],S1[2t+1]*/\
        reinterpret_cast<float2*>(sS1)[32 * (i) + l] = make_float2(_a, _b);\
        float _s2 = _a + _b;                           /* S2[t] */         \
        sS2[32 * (i) + l] = _s2;                                           \
        float _s2n = __shfl_xor_sync(0xffffffffu, _s2, 1);                 \
        if ((l & 1) == 0) sS3[16 * (i) + (l >> 1)] = _s2 + _s2n; /*S3[t/2]*/\
    }
    PRODUCE(0, v0)
    PRODUCE(1, v1)
    PRODUCE(2, v2)
    PRODUCE(3, v3)
    PRODUCE(4, v4)
    PRODUCE(5, v5)
    PRODUCE(6, v6)
    PRODUCE(7, v7)
#undef PRODUCE

    __syncwarp();

    const float u0 = swgt[0], u1 = swgt[1], u2 = swgt[2];
    const float d0 = swgt[3], d1 = swgt[4], d2 = swgt[5];

    float4* outr = reinterpret_cast<float4*>(out + row * (long long)D);

    // Consume phase: c = 128i + 4l + k.
#define CONSUME(i, v)                                                      \
    {                                                                      \
        float r0 = (v).x, r1 = (v).y, r2 = (v).z, r3 = (v).w;              \
        /* up stride 2: k=0 -> x[64i+2l], k=2 -> x[64i+2l+1] */            \
        float2 xu = reinterpret_cast<const float2*>(sx)[32 * (i) + l];     \
        r0 += u0 * xu.x;                                                   \
        r2 += u0 * xu.y;                                                   \
        /* up stride 4: k=0 -> x[32i+l] */                                 \
        r0 += u1 * sx[32 * (i) + l];                                       \
        /* up stride 8: k=0, even lanes -> x[16i+l/2] */                   \
        if ((l & 1) == 0) r0 += u2 * sx[16 * (i) + (l >> 1)];              \
        /* down: out[c] += d_o * S_o[c] for 1 <= c < D/s */                \
        if ((i) < 4) {                                                     \
            float4 a = reinterpret_cast<const float4*>(sS1)[32 * (i) + l]; \
            r0 += d0 * a.x; r1 += d0 * a.y; r2 += d0 * a.z; r3 += d0 * a.w;\
        }                                                                  \
        if ((i) < 2) {                                                     \
            float4 a = reinterpret_cast<const float4*>(sS2)[32 * (i) + l]; \
            r0 += d1 * a.x; r1 += d1 * a.y; r2 += d1 * a.z; r3 += d1 * a.w;\
        }                                                                  \
        if ((i) == 0) {                                                    \
            float4 a = reinterpret_cast<const float4*>(sS3)[l];            \
            r0 += d2 * a.x; r1 += d2 * a.y; r2 += d2 * a.z; r3 += d2 * a.w;\
            if (l == 0)  /* c = 0 is not a down target */                  \
                r0 -= d0 * sS1[0] + d1 * sS2[0] + d2 * sS3[0];             \
        }                                                                  \
        outr[32 * (i) + l] = make_float4(r0, r1, r2, r3);                  \
    }
    CONSUME(0, v0)
    CONSUME(1, v1)
    CONSUME(2, v2)
    CONSUME(3, v3)
    CONSUME(4, v4)
    CONSUME(5, v5)
    CONSUME(6, v6)
    CONSUME(7, v7)
#undef CONSUME
}

extern "C" void kernel_launch(void* const* d_in, const int* in_sizes, int n_in,
                              void* d_out, int out_size)
{
    const float* x  = (const float*)d_in[0];
    const float* uw = (const float*)d_in[1];
    const float* dw = (const float*)d_in[2];
    float* out = (float*)d_out;

    const int rows = in_sizes[0] / D;            // 32768
    const int grid = rows / WARPS_PER_CTA;       // 4096
    harmonic_mixing_kernel<<<grid, THREADS>>>(x, uw, dw, out);
}